// round 2
// baseline (speedup 1.0000x reference)
#include <cuda_runtime.h>
#include <math.h>

#define DGRID 200
#define NCELL 8000000
#define BA 8
#define BB 8
#define BC 40
#define SA 12
#define SB 12
#define SC 44
#define STILE (SA*SB*SC)   /* 6336 */
#define TCELLS (BA*BB*BC)  /* 2560 */
#define NTHREADS 640

#define THX 0.1000002f
#define PS2TH 0.01000004f
#define KNF 600000.0f

// constants derived from the reference (computed in double, truncated to f32):
// PM   = 4/3*3.1415*0.05^3*2700      = 1.41367499999999...
// alpha= ln2/pi, gamma = alpha/sqrt(alpha^2+1)
// ETA  = 2*gamma*sqrt(KN*PM)         = 402.0035...
#define ETA_F   402.00354003906250f      /* (float)(2*gamma*sqrt(600000*PM)) */
#define DTPM_F  7.0737531874049切0e-05f   /* placeholder - defined below properly */
#undef DTPM_F

__device__ __forceinline__ int wrapD(int v) {
    if (v < 0) v += DGRID;
    else if (v >= DGRID) v -= DGRID;
    return v;
}

__global__ void __launch_bounds__(NTHREADS, 2)
dem_step_kernel(const float* __restrict__ xg, const float* __restrict__ yg,
                const float* __restrict__ zg, const float* __restrict__ vxg,
                const float* __restrict__ vyg, const float* __restrict__ vzg,
                const float* __restrict__ mg, float* __restrict__ out,
                float eta, float dtpm, float gpm)
{
    extern __shared__ char smraw[];
    float* sx  = (float*)smraw;
    float* sy  = sx + STILE;
    float* sz  = sy + STILE;
    float* fxs = sz + STILE;
    float* fys = fxs + TCELLS;
    float* fzs = fys + TCELLS;
    unsigned short* lst = (unsigned short*)(fzs + TCELLS);
    int* cnt = (int*)(lst + TCELLS);

    const int tx = threadIdx.x, ty = threadIdx.y, tz = threadIdx.z;
    const int tid = tx + 10*ty + 80*tz;
    const int a0 = blockIdx.z * BA, b0 = blockIdx.y * BB, c0 = blockIdx.x * BC;

    if (tid == 0) *cnt = 0;
    for (int s = tid; s < TCELLS; s += NTHREADS) {
        fxs[s] = 0.f; fys[s] = 0.f; fzs[s] = 0.f;
    }
    // ---- load position tile (with periodic halo of 2) into smem ----
    for (int s = tid; s < STILE; s += NTHREADS) {
        int sc = s % SC; int r = s / SC; int sb = r % SB; int sa = r / SB;
        int ga = wrapD(a0 - 2 + sa);
        int gb = wrapD(b0 - 2 + sb);
        int gc = wrapD(c0 - 2 + sc);
        int g = (ga*DGRID + gb)*DGRID + gc;
        sx[s] = __ldg(xg + g);
        sy[s] = __ldg(yg + g);
        sz[s] = __ldg(zg + g);
    }

    const int la = tz, lb = ty, lc0 = 4*tx;
    const int pbase = ((a0 + la)*DGRID + (b0 + lb))*DGRID + (c0 + lc0);
    const float4 mk4 = *(const float4*)(mg + pbase);
    float mks[4] = {mk4.x, mk4.y, mk4.z, mk4.w};

    __syncthreads();

    // ---- warp-aggregated compaction of masked cells ----
    const int lane = tid & 31;
    const unsigned cidb = (unsigned)((la*BB + lb)*BC + lc0);
    #pragma unroll
    for (int t = 0; t < 4; t++) {
        bool m = (mks[t] != 0.f);
        unsigned bal = __ballot_sync(0xffffffffu, m);
        if (bal) {
            int base = 0;
            int leader = __ffs(bal) - 1;
            if (lane == leader) base = atomicAdd(cnt, __popc(bal));
            base = __shfl_sync(0xffffffffu, base, leader);
            if (m) {
                int pos = base + __popc(bal & ((1u << lane) - 1u));
                lst[pos] = (unsigned short)(cidb + t);
            }
        }
    }
    __syncthreads();

    // ---- force phase: tasks = (masked cell, oa) ----
    const int total = (*cnt) * 5;
    for (int i = tid; i < total; i += NTHREADS) {
        int j  = i / 5;
        int oa = i - j*5;
        int cid = (int)lst[j];
        int pla = cid / (BB*BC);
        int rem = cid - pla*(BB*BC);
        int plb = rem / BC;
        int plc = rem - plb*BC;
        int ctr = ((pla + 2)*SB + (plb + 2))*SC + (plc + 2);
        float xp = sx[ctr], yp = sy[ctr], zp = sz[ctr];
        float fx = 0.f, fy = 0.f, fz = 0.f;
        int rb0 = ctr + (oa - 2)*(SB*SC) - 2*SC - 2;
        #pragma unroll
        for (int ob = 0; ob < 5; ob++) {
            int rbase = rb0 + ob*SC;
            float xr[5];
            xr[0] = sx[rbase+0]; xr[1] = sx[rbase+1]; xr[2] = sx[rbase+2];
            xr[3] = sx[rbase+3]; xr[4] = sx[rbase+4];
            #pragma unroll
            for (int oc = 0; oc < 5; oc++) {
                float dx = xp - xr[oc];
                if (fabsf(dx) < THX) {
                    int q = rbase + oc;
                    float dy = yp - sy[q];
                    if (fabsf(dy) < THX) {
                        float dz = zp - sz[q];
                        float sq = fmaf(dx, dx, fmaf(dy, dy, dz*dz));
                        if (sq > 0.f && sq < PS2TH) {
                            float dist = sqrtf(sq);
                            if (dist < 0.1f) {
                                float dcl = fmaxf(dist, 1e-4f);
                                int qsc = q % SC; int qr = q / SC;
                                int qsb = qr % SB; int qsa = qr / SB;
                                int gqa = wrapD(a0 - 2 + qsa);
                                int gqb = wrapD(b0 - 2 + qsb);
                                int gqc = wrapD(c0 - 2 + qsc);
                                int gq = (gqa*DGRID + gqb)*DGRID + gqc;
                                int gp = ((a0 + pla)*DGRID + (b0 + plb))*DGRID + (c0 + plc);
                                float dvx = __ldg(vxg + gp) - __ldg(vxg + gq);
                                float dvy = __ldg(vyg + gp) - __ldg(vyg + gq);
                                float dvz = __ldg(vzg + gp) - __ldg(vzg + gq);
                                float vn = (dvx*dx + dvy*dy + dvz*dz) / dcl;
                                float coef = 2.0f * (KNF*(dist - 0.1f) + eta*vn) / dcl;
                                fx += coef*dx; fy += coef*dy; fz += coef*dz;
                            }
                        }
                    }
                }
            }
        }
        if (fx != 0.f || fy != 0.f || fz != 0.f) {
            atomicAdd(&fxs[cid], fx);
            atomicAdd(&fys[cid], fy);
            atomicAdd(&fzs[cid], fz);
        }
    }
    __syncthreads();

    // ---- update + writeback (all cells) ----
    const float4 vx4 = *(const float4*)(vxg + pbase);
    const float4 vy4 = *(const float4*)(vyg + pbase);
    const float4 vz4 = *(const float4*)(vzg + pbase);
    float vxs[4] = {vx4.x, vx4.y, vx4.z, vx4.w};
    float vys[4] = {vy4.x, vy4.y, vy4.z, vy4.w};
    float vzs[4] = {vz4.x, vz4.y, vz4.z, vz4.w};
    const int cbase = ((la + 2)*SB + (lb + 2))*SC + (lc0 + 2);

    float ox[4], oy[4], oz[4], ovx[4], ovy[4], ovz[4];
    #pragma unroll
    for (int t = 0; t < 4; t++) {
        float x = sx[cbase + t], y = sy[cbase + t], z = sz[cbase + t];
        float vx = vxs[t], vy = vys[t], vz = vzs[t], m = mks[t];
        int cid = (int)cidb + t;
        float fx = fxs[cid], fy = fys[cid], fz = fzs[cid];

        float lft = (x > 0.1f && x < 0.15f) ? 1.f : 0.f;
        float rgt = (x > 9.9f) ? 1.f : 0.f;
        float rtx = ((x - 10.0f) + 0.05f) + 0.05f;
        float fxb = KNF*lft*(0.15f - x) - KNF*rgt*rtx - eta*vx*lft - eta*vx*rgt;

        float bot = (y > 0.1f && y < 0.15f) ? 1.f : 0.f;
        float top = (y > 9.9f) ? 1.f : 0.f;
        float rty = ((y - 10.0f) + 0.05f) + 0.05f;
        float fyb = KNF*bot*(0.15f - y) - KNF*top*rty - eta*vy*bot - eta*vy*top;

        float fwd = (z > 0.1f && z < 0.15f) ? 1.f : 0.f;
        float bck = (z > 9.9f) ? 1.f : 0.f;
        float rtz = ((z - 10.0f) + 0.05f) + 0.05f;
        float fzb = KNF*fwd*(0.15f - z) - KNF*bck*rtz - eta*vz*fwd - eta*vz*bck;

        float vx2 = vx + dtpm * (m * (fxb - fx));
        float vy2 = vy + dtpm * (m * (fyb - fy));
        float vz2 = vz + dtpm * (m * ((gpm - fz) + fzb));
        float x2 = x + 1e-4f * vx2;
        float y2 = y + 1e-4f * vy2;
        float z2 = z + 1e-4f * vz2;
        ox[t] = x2; oy[t] = y2; oz[t] = z2;
        ovx[t] = vx2; ovy[t] = vy2; ovz[t] = vz2;
    }
    *(float4*)(out + (size_t)0*NCELL + pbase) = make_float4(ox[0], ox[1], ox[2], ox[3]);
    *(float4*)(out + (size_t)1*NCELL + pbase) = make_float4(oy[0], oy[1], oy[2], oy[3]);
    *(float4*)(out + (size_t)2*NCELL + pbase) = make_float4(oz[0], oz[1], oz[2], oz[3]);
    *(float4*)(out + (size_t)3*NCELL + pbase) = make_float4(ovx[0], ovx[1], ovx[2], ovx[3]);
    *(float4*)(out + (size_t)4*NCELL + pbase) = make_float4(ovy[0], ovy[1], ovy[2], ovy[3]);
    *(float4*)(out + (size_t)5*NCELL + pbase) = make_float4(ovz[0], ovz[1], ovz[2], ovz[3]);
}

extern "C" void kernel_launch(void* const* d_in, const int* in_sizes, int n_in,
                              void* d_out, int out_size)
{
    const float* xg  = (const float*)d_in[0];
    const float* yg  = (const float*)d_in[1];
    const float* zg  = (const float*)d_in[2];
    const float* vxg = (const float*)d_in[3];
    const float* vyg = (const float*)d_in[4];
    const float* vzg = (const float*)d_in[5];
    const float* mg  = (const float*)d_in[6];
    float* out = (float*)d_out;

    // constants replicated from the reference (double precision, then f32)
    const double PMd   = 4.0/3.0 * 3.1415 * 0.05*0.05*0.05 * 2700.0;
    const double alpha = 0.6931471805599453 / 3.141592653589793; // -ln(0.5)/pi
    const double gamm  = alpha / sqrt(alpha*alpha + 1.0);
    const double ETAd  = 2.0 * gamm * sqrt(600000.0 * PMd);
    const float eta  = (float)ETAd;
    const float dtpm = (float)(1e-4 / PMd);
    const float gpm  = (float)(-9.8 * PMd);

    const size_t smem_bytes =
        (size_t)(3*STILE + 3*TCELLS) * sizeof(float) +
        (size_t)TCELLS * sizeof(unsigned short) +
        sizeof(int);

    (void)cudaFuncSetAttribute(dem_step_kernel,
                               cudaFuncAttributeMaxDynamicSharedMemorySize,
                               (int)smem_bytes);

    dim3 grid(DGRID/BC, DGRID/BB, DGRID/BA);  // (5, 25, 25)
    dim3 block(10, 8, 8);                     // 640 threads, c-block of 4
    dem_step_kernel<<<grid, block, smem_bytes>>>(xg, yg, zg, vxg, vyg, vzg, mg,
                                                 out, eta, dtpm, gpm);
}